// round 12
// baseline (speedup 1.0000x reference)
#include <cuda_runtime.h>

#define BB 4
#define TT 32
#define DD 256
#define NN 1024
#define GROUP 32      // CTAs per batch group
#define COLS 32       // G columns owned per CTA
#define NTHR 512      // threads in main kernel (16 warps)
#define CPW 2         // columns per warp (register-resident)

// ---------------- device scratch ----------------
__device__ float    g_xn[BB*TT*NN];        // relu(ln(x@E))
__device__ float    g_tn[BB*TT*NN];        // relu(ln(targets@E))
__device__ float    g_p[2][BB][NN];        // p1 / p2 exchange buffers
__device__ float    g_reason[BB*TT*NN];    // max(p1,p2,p3)
__device__ unsigned g_flag[2][BB][32][32]; // ready flags, 128B padded per part

// ---------------- sync primitives ----------------
__device__ __forceinline__ void st_release(unsigned* p, unsigned v) {
  asm volatile("st.release.gpu.global.u32 [%0], %1;" :: "l"(p), "r"(v) : "memory");
}
__device__ __forceinline__ unsigned ld_acquire(const unsigned* p) {
  unsigned v;
  asm volatile("ld.acquire.gpu.global.u32 %0, [%1];" : "=r"(v) : "l"(p) : "memory");
  return v;
}

// ---------------- kernel 1: neurons = relu(layernorm(X @ E)) ----------------
// 1024 threads, 2 rows per block (E reuse), grid = 64.
__device__ __forceinline__ void ln_store(float v, float* dst, float2* red) {
  int tid = threadIdx.x, w = tid >> 5, l = tid & 31;
  float s1 = v, s2 = v*v;
#pragma unroll
  for (int o = 16; o; o >>= 1) {
    s1 += __shfl_xor_sync(0xffffffffu, s1, o);
    s2 += __shfl_xor_sync(0xffffffffu, s2, o);
  }
  if (l == 0) { red[w].x = s1; red[w].y = s2; }
  __syncthreads();
  float t1 = 0.f, t2 = 0.f;
#pragma unroll
  for (int i = 0; i < 32; ++i) { t1 += red[i].x; t2 += red[i].y; }
  float mu  = t1 * (1.0f/NN);
  float inv = rsqrtf(t2*(1.0f/NN) - mu*mu + 1e-5f);
  dst[tid] = fmaxf(0.f, (v - mu)*inv);
  __syncthreads();   // before red[] reuse
}

__global__ void __launch_bounds__(1024) prep_kernel(const float* __restrict__ x_seq,
                                                    const float* __restrict__ targets,
                                                    const float* __restrict__ E) {
  __shared__ float xs[2][DD], ts[2][DD];
  __shared__ float2 red[32];
  int r0 = blockIdx.x * 2;         // rows r0, r0+1
  int tid = threadIdx.x;           // column 0..1023

  if (blockIdx.x == 0) {           // reset flags for this launch
    unsigned* f = (unsigned*)g_flag;
    for (int i = tid; i < 2*BB*32*32; i += 1024) f[i] = 0u;
  }

  if (tid < DD) {
    xs[0][tid] = x_seq[r0*DD + tid];
    ts[0][tid] = targets[r0*DD + tid];
  } else if (tid < 2*DD) {
    int c = tid - DD;
    xs[1][c] = x_seq[(r0+1)*DD + c];
    ts[1][c] = targets[(r0+1)*DD + c];
  }
  __syncthreads();

  float a00 = 0.f, a01 = 0.f, a10 = 0.f, a11 = 0.f;
#pragma unroll 8
  for (int k = 0; k < DD; ++k) {
    float e = __ldg(E + k*NN + tid);
    a00 += xs[0][k]*e; a01 += ts[0][k]*e;
    a10 += xs[1][k]*e; a11 += ts[1][k]*e;
  }

  ln_store(a00, g_xn + r0*NN,     red);
  ln_store(a01, g_tn + r0*NN,     red);
  ln_store(a10, g_xn + (r0+1)*NN, red);
  ln_store(a11, g_tn + (r0+1)*NN, red);
}

// ---------------- kernel 2: persistent scan, register-resident G ----------
// CTA (b, part) owns G[:, part*32 .. +31]. 16 warps x 2 cols each.
// Thread (w, l): cols cbase = part*32 + w*2 + {0,1}, rows n = l + 32*j.
__global__ void __launch_bounds__(NTHR, 1) main_kernel() {
  __shared__ float xb[2*NN];       // ping-pong x_neuron vectors
  __shared__ float pb[NN];         // staged p vector
  __shared__ float tb[2][COLS];    // ping-pong 0.5*tn values

  int cta  = blockIdx.x;
  int b    = cta >> 5;
  int part = cta & 31;
  int mbase = part * COLS;
  int tid = threadIdx.x, w = tid >> 5, l = tid & 31;
  int cbase = mbase + w*CPW;

  float gr0[32], gr1[32];
#pragma unroll
  for (int j = 0; j < 32; ++j) {
    int n = l + 32*j;
    gr0[j] = (n == cbase)     ? 0.01f : 0.0f;
    gr1[j] = (n == cbase + 1) ? 0.01f : 0.0f;
  }

  // stage step-0 inputs
  {
    const float* gx = g_xn + (b*TT)*NN;
    for (int i = tid; i < NN; i += NTHR) xb[i] = gx[i];
    if (tid < COLS) tb[0][tid] = 0.5f * g_tn[(b*TT)*NN + mbase + tid];
  }
  __syncthreads();

  for (int t = 0; t < TT; ++t) {
    const float* xc = xb + (t & 1)*NN;
    const float* xp = xb + ((t & 1)^1)*NN;
    float tv0 = tb[t & 1][w*CPW + 0];
    float tv1 = tb[t & 1][w*CPW + 1];
    unsigned tok = (unsigned)(t + 1);

    float acc0 = 0.f, acc1 = 0.f;
    float r0, r1;

    // ---- phase 1: apply pending rank-1 max-update (t>0), compute p1 ----
    if (t > 0) {
#pragma unroll
      for (int j = 0; j < 32; ++j) {
        float xpv = xp[l + 32*j];
        float xcv = xc[l + 32*j];
        gr0[j] = fmaxf(gr0[j], xpv*tv0);
        gr1[j] = fmaxf(gr1[j], xpv*tv1);
        acc0 += xcv*gr0[j];
        acc1 += xcv*gr1[j];
      }
    } else {
#pragma unroll
      for (int j = 0; j < 32; ++j) {
        float xcv = xc[l + 32*j];
        acc0 += xcv*gr0[j];
        acc1 += xcv*gr1[j];
      }
    }
#pragma unroll
    for (int o = 16; o; o >>= 1) {
      acc0 += __shfl_xor_sync(0xffffffffu, acc0, o);
      acc1 += __shfl_xor_sync(0xffffffffu, acc1, o);
    }
    if (l == 0) {
      float2 st; st.x = acc0; st.y = acc1;
      *(float2*)(&g_p[0][b][cbase]) = st;
    }
    r0 = acc0; r1 = acc1;

    // ---- publish p1 (flag per part, no atomics) ----
    __syncthreads();
    if (tid == 0) st_release(&g_flag[0][b][part][0], tok);

    // prefetch next-step inputs in the wait shadow
    if (t + 1 < TT) {
      const float* gx2 = g_xn + (b*TT + t + 1)*NN;
      float* xn2 = xb + ((t + 1) & 1)*NN;
      for (int i = tid; i < NN; i += NTHR) xn2[i] = gx2[i];
      if (tid < COLS)
        tb[(t + 1) & 1][tid] = 0.5f * g_tn[(b*TT + t + 1)*NN + mbase + tid];
    }

    // ---- distributed wait + stage p1: warp w handles parts 2w, 2w+1 ----
    {
      unsigned ready = (l < 2) ? 0u : 1u;
      const unsigned* fp = &g_flag[0][b][2*w + (l & 1)][0];
      do {
        if (!ready) ready = (ld_acquire(fp) >= tok) ? 1u : 0u;
      } while (!__all_sync(0xffffffffu, ready));
      const float2* gp2 = (const float2*)&g_p[0][b][0];
      ((float2*)pb)[32*w + l] = __ldcg(gp2 + 32*w + l);
    }
    __syncthreads();

    // ---- phase 2: p2 = p1 . G ----
    acc0 = 0.f; acc1 = 0.f;
#pragma unroll
    for (int j = 0; j < 32; ++j) {
      float pv = pb[l + 32*j];
      acc0 += pv*gr0[j];
      acc1 += pv*gr1[j];
    }
#pragma unroll
    for (int o = 16; o; o >>= 1) {
      acc0 += __shfl_xor_sync(0xffffffffu, acc0, o);
      acc1 += __shfl_xor_sync(0xffffffffu, acc1, o);
    }
    if (l == 0) {
      float2 st; st.x = acc0; st.y = acc1;
      *(float2*)(&g_p[1][b][cbase]) = st;
    }
    r0 = fmaxf(r0, acc0); r1 = fmaxf(r1, acc1);

    // ---- publish p2 ----
    __syncthreads();
    if (tid == 0) st_release(&g_flag[1][b][part][0], tok);

    // ---- distributed wait + stage p2 ----
    {
      unsigned ready = (l < 2) ? 0u : 1u;
      const unsigned* fp = &g_flag[1][b][2*w + (l & 1)][0];
      do {
        if (!ready) ready = (ld_acquire(fp) >= tok) ? 1u : 0u;
      } while (!__all_sync(0xffffffffu, ready));
      const float2* gp2 = (const float2*)&g_p[1][b][0];
      ((float2*)pb)[32*w + l] = __ldcg(gp2 + 32*w + l);
    }
    __syncthreads();

    // ---- phase 3: p3 = p2 . G (column-local) ----
    acc0 = 0.f; acc1 = 0.f;
#pragma unroll
    for (int j = 0; j < 32; ++j) {
      float pv = pb[l + 32*j];
      acc0 += pv*gr0[j];
      acc1 += pv*gr1[j];
    }
#pragma unroll
    for (int o = 16; o; o >>= 1) {
      acc0 += __shfl_xor_sync(0xffffffffu, acc0, o);
      acc1 += __shfl_xor_sync(0xffffffffu, acc1, o);
    }
    r0 = fmaxf(r0, acc0); r1 = fmaxf(r1, acc1);

    if (l == 0) {
      float2 st; st.x = r0; st.y = r1;
      *(float2*)(&g_reason[(b*TT + t)*NN + cbase]) = st;
    }
    // next iteration's xb/tb staged above; the post-poll syncthreads ordered them
  }
}

// ---------------- kernel 3: y = relu(reasoning @ Dy) ----------------
__global__ void __launch_bounds__(256) out_kernel(const float* __restrict__ Dy,
                                                  float* __restrict__ out) {
  __shared__ float rs[4*NN];
  int rbase = blockIdx.x * 4;      // grid 32 -> 128 rows
  int tid = threadIdx.x;
  int c4 = tid & 63;               // float4 column group
  int r  = tid >> 6;               // row within block (0..3)
  for (int i = tid; i < 4*NN; i += 256) rs[i] = g_reason[rbase*NN + i];
  __syncthreads();

  const float4* Dy4 = (const float4*)Dy;  // [1024][64] float4
  const float* rr = rs + r*NN;
  float4 a = make_float4(0.f,0.f,0.f,0.f);
#pragma unroll 8
  for (int n = 0; n < NN; ++n) {
    float4 d = Dy4[n*64 + c4];
    float pv = rr[n];
    a.x += pv*d.x; a.y += pv*d.y; a.z += pv*d.z; a.w += pv*d.w;
  }
  float4 o;
  o.x = fmaxf(a.x,0.f); o.y = fmaxf(a.y,0.f);
  o.z = fmaxf(a.z,0.f); o.w = fmaxf(a.w,0.f);
  ((float4*)(out + (rbase + r)*DD))[c4] = o;
}

// ---------------- launch ----------------
extern "C" void kernel_launch(void* const* d_in, const int* in_sizes, int n_in,
                              void* d_out, int out_size) {
  const float* x_seq   = (const float*)d_in[0];  // [4,32,256]
  const float* targets = (const float*)d_in[1];  // [4,32,256]
  const float* E       = (const float*)d_in[2];  // [256,1024]
  const float* Dy      = (const float*)d_in[3];  // [1024,256]
  float* out = (float*)d_out;                    // [4,32,256]

  prep_kernel<<<BB*TT/2, 1024>>>(x_seq, targets, E);   // also resets flags
  main_kernel<<<BB*GROUP, NTHR>>>();
  out_kernel<<<32, 256>>>(Dy, out);
}